// round 12
// baseline (speedup 1.0000x reference)
#include <cuda_runtime.h>
#include <math.h>
#include <stdint.h>

#define HID 128
#define NNODE 20000
#define NEDGE 50000
#define BNB 160

// ---------------- scratch (device globals) ----------------
__device__ float g_pooled[NNODE * HID];
__device__ float g_hkan[NNODE * HID];
__device__ float g_hatt[NNODE * HID];
__device__ float g_res[NNODE * HID];
__device__ float g_h[NNODE * HID];
__device__ float g_P1[NNODE * HID];
__device__ float g_QKV[NNODE * 384];
__device__ float g_actN[NNODE * 1152];
__device__ float g_actE[(size_t)NEDGE * 1152];
__device__ float g_alpha[NEDGE];
__device__ float g_Wn[128 * 1152];
__device__ float g_Wp1[128 * 1152];
__device__ float g_Wp2[128 * 1152];
__device__ float g_Wqkv[384 * 128];
__device__ float g_bqkv[384];
__device__ float g_part[BNB * 256];
__device__ float g_mu[128];
__device__ float g_rstd[128];

// ---------------- math helpers ----------------
static __device__ __forceinline__ float knot(int i) {
    return (float)(i - 3) * 0.4f - 1.0f;
}

static __device__ __forceinline__ void bspline8(float x, float* out) {
    float b[11];
#pragma unroll
    for (int j = 0; j < 11; j++)
        b[j] = (x >= knot(j) && x < knot(j + 1)) ? 1.0f : 0.0f;
#pragma unroll
    for (int k = 1; k <= 3; k++) {
#pragma unroll
        for (int j = 0; j < 11 - k; j++) {
            float linv = 1.0f / (knot(j + k) - knot(j));
            float rinv = 1.0f / (knot(j + k + 1) - knot(j + 1));
            b[j] = (x - knot(j)) * linv * b[j] + (knot(j + k + 1) - x) * rinv * b[j + 1];
        }
    }
#pragma unroll
    for (int k = 0; k < 8; k++) out[k] = b[k];
}

static __device__ __forceinline__ float silu_f(float x) {
    return x / (1.0f + expf(-x));
}

static __device__ __forceinline__ float gelu_f(float x) {
    return 0.5f * x * (1.0f + erff(x * 0.7071067811865475f));
}

static __device__ __forceinline__ uint32_t frag(float v) {
    uint32_t r;
    asm("cvt.rna.tf32.f32 %0, %1;" : "=r"(r) : "f"(v));
    return r;
}

static __device__ __forceinline__ void cp_async16(void* smem, const void* gmem) {
    uint32_t s = (uint32_t)__cvta_generic_to_shared(smem);
    asm volatile("cp.async.cg.shared.global [%0], [%1], 16;\n" ::"r"(s), "l"(gmem));
}
#define CP_COMMIT asm volatile("cp.async.commit_group;\n" ::)
#define CP_WAIT1 asm volatile("cp.async.wait_group 1;\n" ::)

// KAN2 contribution of one value at column col
static __device__ __forceinline__ float kan2_term(float v, int col,
                                                  const float* __restrict__ b2,
                                                  const float* __restrict__ s2) {
    float s = silu_f(v) * b2[col];
    float bs[8];
    bspline8(v, bs);
    const float* sp = s2 + col * 8;
#pragma unroll
    for (int k = 0; k < 8; k++) s += bs[k] * sp[k];
    return s;
}

// ---------------- tf32 tensor-core GEMM ----------------
// C[M, ldc] = A[M,K] @ W[N,K]^T (+bias); N-tile = blockIdx.y
// epilogue options:
//   fuse 0: C = acc (+bias) (+addMat[addIdx[r]])
//   fuse 1: C = gelu(...)
//   fuse 2: alphaOut[r] = sigmoid( KAN2(gelu(...)) ) ; C not written
__global__ __launch_bounds__(256) void kgemm(
    const float* __restrict__ A, const float* __restrict__ W,
    const float* __restrict__ bias, float* __restrict__ C,
    int M, int K, int ldc, int fuse,
    const float* __restrict__ addMat, const int* __restrict__ addIdx,
    float* __restrict__ alphaOut, const float* __restrict__ b2,
    const float* __restrict__ s2)
{
    __shared__ float As[2][128][20];
    __shared__ float Ws[2][128][20];
    __shared__ float sm_alpha[128];
    const int bm = blockIdx.x * 128;
    const int bn = blockIdx.y * 128;
    const int tid = threadIdx.x;
    const int warp = tid >> 5, lane = tid & 31;
    const int wm = (warp >> 1) * 32, wn = (warp & 1) * 64;

    const int lr = tid >> 1;
    const int lo = (tid & 1) * 8;
    int arow = bm + lr;
    if (arow >= M) arow = M - 1;
    const float* Abase = A + (size_t)arow * K;
    const float* Wbase = W + (size_t)(bn + lr) * K;

#define LOADTILE(buf, k0)                                          \
    do {                                                           \
        cp_async16(&As[buf][lr][lo], Abase + (k0) + lo);           \
        cp_async16(&As[buf][lr][lo + 4], Abase + (k0) + lo + 4);   \
        cp_async16(&Ws[buf][lr][lo], Wbase + (k0) + lo);           \
        cp_async16(&Ws[buf][lr][lo + 4], Wbase + (k0) + lo + 4);   \
    } while (0)

    float acc[2][8][4];
#pragma unroll
    for (int t = 0; t < 2; t++)
#pragma unroll
        for (int n = 0; n < 8; n++)
#pragma unroll
            for (int v = 0; v < 4; v++) acc[t][n][v] = 0.0f;

    LOADTILE(0, 0);
    CP_COMMIT;

    const int nk = K >> 4;
    for (int kc = 0; kc < nk; kc++) {
        const int buf = kc & 1;
        if (kc + 1 < nk) LOADTILE(buf ^ 1, (kc + 1) * 16);
        CP_COMMIT;
        CP_WAIT1;
        __syncthreads();

#pragma unroll
        for (int ks = 0; ks < 2; ks++) {
            const int kk = ks * 8;
            const int r0 = wm + (lane >> 2);
            const int c0 = kk + (lane & 3);
            uint32_t ua[2][4];
#pragma unroll
            for (int t = 0; t < 2; t++) {
                ua[t][0] = frag(As[buf][r0 + t * 16][c0]);
                ua[t][1] = frag(As[buf][r0 + t * 16 + 8][c0]);
                ua[t][2] = frag(As[buf][r0 + t * 16][c0 + 4]);
                ua[t][3] = frag(As[buf][r0 + t * 16 + 8][c0 + 4]);
            }
#pragma unroll
            for (int n = 0; n < 8; n++) {
                const int nr = wn + n * 8 + (lane >> 2);
                uint32_t ub0 = frag(Ws[buf][nr][kk + (lane & 3)]);
                uint32_t ub1 = frag(Ws[buf][nr][kk + (lane & 3) + 4]);
#pragma unroll
                for (int t = 0; t < 2; t++) {
                    asm volatile(
                        "mma.sync.aligned.m16n8k8.row.col.f32.tf32.tf32.f32 "
                        "{%0,%1,%2,%3},{%4,%5,%6,%7},{%8,%9},{%0,%1,%2,%3};"
                        : "+f"(acc[t][n][0]), "+f"(acc[t][n][1]),
                          "+f"(acc[t][n][2]), "+f"(acc[t][n][3])
                        : "r"(ua[t][0]), "r"(ua[t][1]), "r"(ua[t][2]), "r"(ua[t][3]),
                          "r"(ub0), "r"(ub1));
                }
            }
        }
        __syncthreads();
    }
#undef LOADTILE

    if (fuse == 2) {
        // ---- fused KAN2 + sigmoid -> alpha, z1 never stored ----
        if (tid < 128) sm_alpha[tid] = 0.0f;
        __syncthreads();
        float srow[2][2] = {{0.0f, 0.0f}, {0.0f, 0.0f}};
#pragma unroll
        for (int t = 0; t < 2; t++) {
            const int r = bm + wm + t * 16 + (lane >> 2);
            const int r2 = r + 8;
            const float* add0 =
                (addMat && r < M) ? addMat + (size_t)(addIdx ? addIdx[r] : r) * ldc : nullptr;
            const float* add1 =
                (addMat && r2 < M) ? addMat + (size_t)(addIdx ? addIdx[r2] : r2) * ldc : nullptr;
#pragma unroll
            for (int n = 0; n < 8; n++) {
                const int col = bn + wn + n * 8 + (lane & 3) * 2;
                float v0 = gelu_f(acc[t][n][0] + (add0 ? add0[col] : 0.0f));
                float v1 = gelu_f(acc[t][n][1] + (add0 ? add0[col + 1] : 0.0f));
                float v2 = gelu_f(acc[t][n][2] + (add1 ? add1[col] : 0.0f));
                float v3 = gelu_f(acc[t][n][3] + (add1 ? add1[col + 1] : 0.0f));
                srow[t][0] += kan2_term(v0, col, b2, s2) + kan2_term(v1, col + 1, b2, s2);
                srow[t][1] += kan2_term(v2, col, b2, s2) + kan2_term(v3, col + 1, b2, s2);
            }
        }
        // reduce across the 4 lanes sharing each row
#pragma unroll
        for (int o = 1; o < 4; o <<= 1) {
            srow[0][0] += __shfl_xor_sync(0xffffffffu, srow[0][0], o);
            srow[0][1] += __shfl_xor_sync(0xffffffffu, srow[0][1], o);
            srow[1][0] += __shfl_xor_sync(0xffffffffu, srow[1][0], o);
            srow[1][1] += __shfl_xor_sync(0xffffffffu, srow[1][1], o);
        }
        if ((lane & 3) == 0) {
            const int rl = wm + (lane >> 2);
            atomicAdd(&sm_alpha[rl], srow[0][0]);
            atomicAdd(&sm_alpha[rl + 8], srow[0][1]);
            atomicAdd(&sm_alpha[rl + 16], srow[1][0]);
            atomicAdd(&sm_alpha[rl + 24], srow[1][1]);
        }
        __syncthreads();
        if (tid < 128) {
            const int r = bm + tid;
            if (r < M) alphaOut[r] = 1.0f / (1.0f + expf(-sm_alpha[tid]));
        }
        return;
    }

    // ---- standard epilogue ----
#pragma unroll
    for (int t = 0; t < 2; t++) {
        const int r = bm + wm + t * 16 + (lane >> 2);
        const int r2 = r + 8;
        const float* add0 = nullptr;
        const float* add1 = nullptr;
        if (addMat) {
            if (r < M) add0 = addMat + (size_t)(addIdx ? addIdx[r] : r) * ldc;
            if (r2 < M) add1 = addMat + (size_t)(addIdx ? addIdx[r2] : r2) * ldc;
        }
#pragma unroll
        for (int n = 0; n < 8; n++) {
            const int col = bn + wn + n * 8 + (lane & 3) * 2;
            float bz0 = bias ? bias[col] : 0.0f;
            float bz1 = bias ? bias[col + 1] : 0.0f;
            float v0 = acc[t][n][0] + bz0 + (add0 ? add0[col] : 0.0f);
            float v1 = acc[t][n][1] + bz1 + (add0 ? add0[col + 1] : 0.0f);
            float v2 = acc[t][n][2] + bz0 + (add1 ? add1[col] : 0.0f);
            float v3 = acc[t][n][3] + bz1 + (add1 ? add1[col + 1] : 0.0f);
            if (fuse == 1) { v0 = gelu_f(v0); v1 = gelu_f(v1); v2 = gelu_f(v2); v3 = gelu_f(v3); }
            if (r < M) {
                C[(size_t)r * ldc + col] = v0;
                C[(size_t)r * ldc + col + 1] = v1;
            }
            if (r2 < M) {
                C[(size_t)r2 * ldc + col] = v2;
                C[(size_t)r2 * ldc + col + 1] = v3;
            }
        }
    }
}

// ---------------- small kernels ----------------
__global__ void k_pack_slice(float* __restrict__ dst, const float* __restrict__ base,
                             const float* __restrict__ spline, int in_total, int c0) {
    int idx = blockIdx.x * blockDim.x + threadIdx.x;
    if (idx >= 128 * 1152) return;
    int o = idx / 1152;
    int c = idx - o * 1152;
    float v;
    if (c < 128) {
        v = base[(size_t)o * in_total + c0 + c];
    } else {
        int ci = (c - 128) >> 3, k = (c - 128) & 7;
        v = spline[((size_t)o * in_total + c0 + ci) * 8 + k];
    }
    dst[idx] = v;
}

__global__ void k_pack_qkv(float* __restrict__ Wd, float* __restrict__ bd,
                           const float* __restrict__ qW, const float* __restrict__ qb,
                           const float* __restrict__ kW, const float* __restrict__ kb,
                           const float* __restrict__ vW, const float* __restrict__ vb) {
    int idx = blockIdx.x * blockDim.x + threadIdx.x;
    if (idx < 384 * 128) {
        int o = idx >> 7, c = idx & 127;
        float v;
        if (o < 128) v = qW[o * 128 + c];
        else if (o < 256) v = kW[(o - 128) * 128 + c];
        else v = vW[(o - 256) * 128 + c];
        Wd[idx] = v;
    }
    if (idx < 384) {
        bd[idx] = (idx < 128) ? qb[idx] : (idx < 256 ? kb[idx - 128] : vb[idx - 256]);
    }
}

__global__ void k_pool_init(float* __restrict__ pooled, const float* __restrict__ h,
                            const float* __restrict__ eps, int l, int total) {
    int idx = blockIdx.x * blockDim.x + threadIdx.x;
    if (idx >= total) return;
    pooled[idx] = (1.0f + eps[l]) * h[idx];
}

__global__ void k_scatter_pool(float* __restrict__ pooled, const float* __restrict__ h,
                               const int* __restrict__ src, const int* __restrict__ dst,
                               int E) {
    int idx = blockIdx.x * blockDim.x + threadIdx.x;
    if (idx >= E * HID) return;
    int e = idx >> 7;
    int f = idx & 127;
    atomicAdd(&pooled[(size_t)src[e] * HID + f], h[(size_t)dst[e] * HID + f]);
}

// KAN act expansion: X[M,128] -> act[M,1152]
__global__ void k_act(float* __restrict__ act, const float* __restrict__ X, int total) {
    int idx = blockIdx.x * blockDim.x + threadIdx.x;
    if (idx >= total) return;
    int n = idx >> 7;
    int i = idx & 127;
    float x = X[idx];
    float* row = act + (size_t)n * 1152;
    row[i] = silu_f(x);
    float bs[8];
    bspline8(x, bs);
    float4* bp = reinterpret_cast<float4*>(row + 128 + i * 8);
    bp[0] = make_float4(bs[0], bs[1], bs[2], bs[3]);
    bp[1] = make_float4(bs[4], bs[5], bs[6], bs[7]);
}

__global__ void k_bn_partial(const float* __restrict__ X, float* __restrict__ part, int Nn) {
    int f = threadIdx.x;
    float s = 0.0f, s2 = 0.0f;
    for (int r = blockIdx.x; r < Nn; r += gridDim.x) {
        float v = X[(size_t)r * HID + f];
        s += v;
        s2 += v * v;
    }
    part[blockIdx.x * 256 + f] = s;
    part[blockIdx.x * 256 + 128 + f] = s2;
}

__global__ void k_bn_final(const float* __restrict__ part, float* __restrict__ mu,
                           float* __restrict__ rstd, int Nn) {
    int f = threadIdx.x;
    float s = 0.0f, s2 = 0.0f;
    for (int b = 0; b < BNB; b++) {
        s += part[b * 256 + f];
        s2 += part[b * 256 + 128 + f];
    }
    float m = s / (float)Nn;
    float v = s2 / (float)Nn - m * m;
    mu[f] = m;
    rstd[f] = rsqrtf(v + 1e-5f);
}

// bn + relu; writes hkan, copy hatt, AND the KAN expansion of hkan into actN
__global__ void k_bn_apply_act(float* __restrict__ X, float* __restrict__ Xcopy,
                               float* __restrict__ actN,
                               const float* __restrict__ mu, const float* __restrict__ rstd,
                               const float* __restrict__ gamma, const float* __restrict__ beta,
                               int total) {
    int idx = blockIdx.x * blockDim.x + threadIdx.x;
    if (idx >= total) return;
    int n = idx >> 7;
    int i = idx & 127;
    float v = (X[idx] - mu[i]) * rstd[i] * gamma[i] + beta[i];
    v = fmaxf(v, 0.0f);
    X[idx] = v;
    Xcopy[idx] = v;
    float* row = actN + (size_t)n * 1152;
    row[i] = silu_f(v);
    float bs[8];
    bspline8(v, bs);
    float4* bp = reinterpret_cast<float4*>(row + 128 + i * 8);
    bp[0] = make_float4(bs[0], bs[1], bs[2], bs[3]);
    bp[1] = make_float4(bs[4], bs[5], bs[6], bs[7]);
}

// attention from node-level QKV + fused KAN expansion of attended into actE
__global__ void k_attn_act(const float* __restrict__ QKV, const int* __restrict__ src,
                           const int* __restrict__ dst, const float* __restrict__ pos,
                           float* __restrict__ actE, int E) {
    int e = blockIdx.x;
    if (e >= E) return;
    int f = threadIdx.x;
    int h = f >> 5;
    __shared__ float logits[4];
    const float* rs = QKV + (size_t)src[e] * 384;
    const float* rd = QKV + (size_t)dst[e] * 384;
    float q = rs[f] + pos[f];
    float k = rd[128 + f] + pos[f];
    float v = rd[256 + f];
    float p = q * k;
#pragma unroll
    for (int o = 16; o > 0; o >>= 1) p += __shfl_down_sync(0xffffffffu, p, o);
    if ((f & 31) == 0) logits[h] = p * 0.17677669529663687f;
    __syncthreads();
    float l0 = logits[0], l1 = logits[1], l2 = logits[2], l3 = logits[3];
    float mx = fmaxf(fmaxf(l0, l1), fmaxf(l2, l3));
    float den = expf(l0 - mx) + expf(l1 - mx) + expf(l2 - mx) + expf(l3 - mx);
    float w = expf(logits[h] - mx) / den;
    float att = w * v;
    float* row = actE + (size_t)e * 1152;
    row[f] = silu_f(att);
    float bs[8];
    bspline8(att, bs);
    float4* bp = reinterpret_cast<float4*>(row + 128 + f * 8);
    bp[0] = make_float4(bs[0], bs[1], bs[2], bs[3]);
    bp[1] = make_float4(bs[4], bs[5], bs[6], bs[7]);
}

__global__ void k_scatter_att(float* __restrict__ hatt, const float* __restrict__ hk,
                              const float* __restrict__ alpha, const int* __restrict__ src,
                              const int* __restrict__ dst, int E) {
    int idx = blockIdx.x * blockDim.x + threadIdx.x;
    if (idx >= E * HID) return;
    int e = idx >> 7;
    int f = idx & 127;
    atomicAdd(&hatt[(size_t)src[e] * HID + f], alpha[e] * hk[(size_t)dst[e] * HID + f]);
}

__global__ void k_ln(const float* __restrict__ Xatt, const float* __restrict__ Res,
                     const float* __restrict__ gamma, const float* __restrict__ beta,
                     float* __restrict__ Hout, int Nn) {
    int n = blockIdx.x;
    if (n >= Nn) return;
    int f = threadIdx.x;
    __shared__ float red[128];
    float x = Xatt[(size_t)n * HID + f] + Res[(size_t)n * HID + f];
    red[f] = x;
    __syncthreads();
#pragma unroll
    for (int o = 64; o > 0; o >>= 1) {
        if (f < o) red[f] += red[f + o];
        __syncthreads();
    }
    float mu = red[0] / 128.0f;
    __syncthreads();
    float d = x - mu;
    red[f] = d * d;
    __syncthreads();
#pragma unroll
    for (int o = 64; o > 0; o >>= 1) {
        if (f < o) red[f] += red[f + o];
        __syncthreads();
    }
    float var = red[0] / 128.0f;
    Hout[(size_t)n * HID + f] = d * rsqrtf(var + 1e-5f) * gamma[f] + beta[f];
}

__global__ void k_clf(const float* __restrict__ H, const float* __restrict__ W,
                      const float* __restrict__ b, float* __restrict__ out, int Nn) {
    int n = blockIdx.x;
    if (n >= Nn) return;
    int o = threadIdx.x >> 5;
    int lane = threadIdx.x & 31;
    float s = 0.0f;
#pragma unroll
    for (int ii = 0; ii < 4; ii++) {
        int i = lane + 32 * ii;
        s += H[(size_t)n * HID + i] * W[o * HID + i];
    }
#pragma unroll
    for (int of = 16; of > 0; of >>= 1) s += __shfl_down_sync(0xffffffffu, s, of);
    if (lane == 0) out[(size_t)n * 10 + o] = s + b[o];
}

// ---------------- launch ----------------
extern "C" void kernel_launch(void* const* d_in, const int* in_sizes, int n_in,
                              void* d_out, int out_size) {
    const float* x = (const float*)d_in[0];
    const int* src = (const int*)d_in[1];
    const int* dst = (const int*)d_in[2];
    const float* eps = (const float*)d_in[3];
    const float* kan_base = (const float*)d_in[4];
    const float* kan_spline = (const float*)d_in[5];
    const float* bn_gamma = (const float*)d_in[6];
    const float* bn_beta = (const float*)d_in[7];
    const float* ln_gamma = (const float*)d_in[8];
    const float* ln_beta = (const float*)d_in[9];
    const float* qW = (const float*)d_in[10];
    const float* qb = (const float*)d_in[11];
    const float* kW = (const float*)d_in[12];
    const float* kb = (const float*)d_in[13];
    const float* vW = (const float*)d_in[14];
    const float* vb = (const float*)d_in[15];
    const float* pos = (const float*)d_in[16];
    const float* ak1b = (const float*)d_in[17];
    const float* ak1s = (const float*)d_in[18];
    const float* ak2b = (const float*)d_in[19];
    const float* ak2s = (const float*)d_in[20];
    const float* skip_W = (const float*)d_in[21];
    const float* skip_b = (const float*)d_in[22];
    const float* clf_W = (const float*)d_in[23];
    const float* clf_b = (const float*)d_in[24];
    float* out = (float*)d_out;

    const int N = in_sizes[0] / HID;
    const int E = in_sizes[1];

    float *p_pooled, *p_hkan, *p_hatt, *p_res, *p_h, *p_P1, *p_QKV, *p_actN, *p_actE;
    float *p_alpha;
    float *p_Wn, *p_Wp1, *p_Wp2, *p_Wqkv, *p_bqkv, *p_part, *p_mu, *p_rstd;
    cudaGetSymbolAddress((void**)&p_pooled, g_pooled);
    cudaGetSymbolAddress((void**)&p_hkan, g_hkan);
    cudaGetSymbolAddress((void**)&p_hatt, g_hatt);
    cudaGetSymbolAddress((void**)&p_res, g_res);
    cudaGetSymbolAddress((void**)&p_h, g_h);
    cudaGetSymbolAddress((void**)&p_P1, g_P1);
    cudaGetSymbolAddress((void**)&p_QKV, g_QKV);
    cudaGetSymbolAddress((void**)&p_actN, g_actN);
    cudaGetSymbolAddress((void**)&p_actE, g_actE);
    cudaGetSymbolAddress((void**)&p_alpha, g_alpha);
    cudaGetSymbolAddress((void**)&p_Wn, g_Wn);
    cudaGetSymbolAddress((void**)&p_Wp1, g_Wp1);
    cudaGetSymbolAddress((void**)&p_Wp2, g_Wp2);
    cudaGetSymbolAddress((void**)&p_Wqkv, g_Wqkv);
    cudaGetSymbolAddress((void**)&p_bqkv, g_bqkv);
    cudaGetSymbolAddress((void**)&p_part, g_part);
    cudaGetSymbolAddress((void**)&p_mu, g_mu);
    cudaGetSymbolAddress((void**)&p_rstd, g_rstd);

    const int T = 256;
    const int nh = N * HID;
    const int eh = E * HID;
    const int gN = (N + 127) / 128;
    const int gE = (E + 127) / 128;
    const int gPack = (128 * 1152 + T - 1) / T;

    for (int l = 0; l < 2; l++) {
        const float* h_in = (l == 0) ? x : p_h;

        // weight packing
        k_pack_slice<<<gPack, T>>>(p_Wn, kan_base + (size_t)l * 128 * 128,
                                   kan_spline + (size_t)l * 128 * 128 * 8, 128, 0);
        k_pack_slice<<<gPack, T>>>(p_Wp1, ak1b + (size_t)l * 128 * 256,
                                   ak1s + (size_t)l * 128 * 256 * 8, 256, 0);
        k_pack_slice<<<gPack, T>>>(p_Wp2, ak1b + (size_t)l * 128 * 256,
                                   ak1s + (size_t)l * 128 * 256 * 8, 256, 128);
        k_pack_qkv<<<(384 * 128 + T - 1) / T, T>>>(p_Wqkv, p_bqkv,
                                                   qW + (size_t)l * 16384, qb + l * 128,
                                                   kW + (size_t)l * 16384, kb + l * 128,
                                                   vW + (size_t)l * 16384, vb + l * 128);

        // GIN aggregation
        k_pool_init<<<(nh + T - 1) / T, T>>>(p_pooled, h_in, eps, l, nh);
        k_scatter_pool<<<(eh + T - 1) / T, T>>>(p_pooled, h_in, src, dst, E);

        // node KAN
        k_act<<<(nh + T - 1) / T, T>>>(p_actN, p_pooled, nh);
        kgemm<<<dim3(gN, 1), 256>>>(p_actN, p_Wn, nullptr, p_hkan, N, 1152, 128, 0,
                                    nullptr, nullptr, nullptr, nullptr, nullptr);

        // BatchNorm + relu (fills hatt copy + actN expansion of hkan)
        k_bn_partial<<<BNB, 128>>>(p_hkan, p_part, N);
        k_bn_final<<<1, 128>>>(p_part, p_mu, p_rstd, N);
        k_bn_apply_act<<<(nh + T - 1) / T, T>>>(p_hkan, p_hatt, p_actN, p_mu, p_rstd,
                                                bn_gamma + l * 128, bn_beta + l * 128, nh);

        // node-level first-half of edge KAN1: P1[n] = kan1_firsthalf(hkan[n])
        kgemm<<<dim3(gN, 1), 256>>>(p_actN, p_Wp1, nullptr, p_P1, N, 1152, 128, 0,
                                    nullptr, nullptr, nullptr, nullptr, nullptr);

        // node-level QKV
        kgemm<<<dim3(gN, 3), 256>>>(p_hkan, p_Wqkv, p_bqkv, p_QKV, N, 128, 384, 0,
                                    nullptr, nullptr, nullptr, nullptr, nullptr);

        // attention + fused edge-act expansion
        k_attn_act<<<E, 128>>>(p_QKV, src, dst, pos + l * 128, p_actE, E);

        // edge KAN1 second-half + gelu + KAN2 + sigmoid, all fused -> alpha
        kgemm<<<dim3(gE, 1), 256>>>(p_actE, p_Wp2, nullptr, nullptr, E, 1152, 128, 2,
                                    p_P1, src, p_alpha, ak2b + l * 128, ak2s + l * 1024);

        // attention aggregation (hatt pre-filled by bn_apply_act)
        k_scatter_att<<<(eh + T - 1) / T, T>>>(p_hatt, p_hkan, p_alpha, src, dst, E);

        // residual + LayerNorm
        const float* resp;
        if (l == 0) {
            kgemm<<<dim3(gN, 1), 256>>>(x, skip_W, skip_b, p_res, N, 128, 128, 0,
                                        nullptr, nullptr, nullptr, nullptr, nullptr);
            resp = p_res;
        } else {
            resp = p_h;
        }
        k_ln<<<N, 128>>>(p_hatt, resp, ln_gamma + l * 128, ln_beta + l * 128, p_h, N);
    }

    k_clf<<<N, 320>>>(p_h, clf_W, clf_b, out, N);
}

// round 13
// speedup vs baseline: 1.0279x; 1.0279x over previous
#include <cuda_runtime.h>
#include <math.h>
#include <stdint.h>

#define HID 128
#define NNODE 20000
#define NEDGE 50000
#define BNB 160

// ---------------- scratch (device globals) ----------------
__device__ float g_pooled[NNODE * HID];
__device__ float g_hkan[NNODE * HID];
__device__ float g_hatt[NNODE * HID];
__device__ float g_res[NNODE * HID];
__device__ float g_h[NNODE * HID];
__device__ float g_P1[NNODE * HID];
__device__ float g_QKV[NNODE * 384];
__device__ float g_actN[NNODE * 1152];
__device__ float g_actE[(size_t)NEDGE * 1152];
__device__ float g_alpha[NEDGE];
__device__ float g_Wn[128 * 1152];
__device__ float g_Wp1[128 * 1152];
__device__ float g_Wp2[128 * 1152];
__device__ float g_Wqkv[384 * 128];
__device__ float g_bqkv[384];
__device__ float g_part[BNB * 256];
__device__ float g_mu[128];
__device__ float g_rstd[128];

// ---------------- math helpers ----------------
static __device__ __forceinline__ float knot(int i) {
    return (float)(i - 3) * 0.4f - 1.0f;
}

static __device__ __forceinline__ void bspline8(float x, float* out) {
    float b[11];
#pragma unroll
    for (int j = 0; j < 11; j++)
        b[j] = (x >= knot(j) && x < knot(j + 1)) ? 1.0f : 0.0f;
#pragma unroll
    for (int k = 1; k <= 3; k++) {
#pragma unroll
        for (int j = 0; j < 11 - k; j++) {
            float linv = 1.0f / (knot(j + k) - knot(j));
            float rinv = 1.0f / (knot(j + k + 1) - knot(j + 1));
            b[j] = (x - knot(j)) * linv * b[j] + (knot(j + k + 1) - x) * rinv * b[j + 1];
        }
    }
#pragma unroll
    for (int k = 0; k < 8; k++) out[k] = b[k];
}

static __device__ __forceinline__ float silu_f(float x) {
    return x / (1.0f + expf(-x));
}

static __device__ __forceinline__ float gelu_f(float x) {
    return 0.5f * x * (1.0f + erff(x * 0.7071067811865475f));
}

static __device__ __forceinline__ uint32_t frag(float v) {
    uint32_t r;
    asm("cvt.rna.tf32.f32 %0, %1;" : "=r"(r) : "f"(v));
    return r;
}

static __device__ __forceinline__ void cp_async16(void* smem, const void* gmem) {
    uint32_t s = (uint32_t)__cvta_generic_to_shared(smem);
    asm volatile("cp.async.cg.shared.global [%0], [%1], 16;\n" ::"r"(s), "l"(gmem));
}
#define CP_COMMIT asm volatile("cp.async.commit_group;\n" ::)
#define CP_WAIT1 asm volatile("cp.async.wait_group 1;\n" ::)

// KAN2 contribution of one value at column col
static __device__ __forceinline__ float kan2_term(float v, int col,
                                                  const float* __restrict__ b2,
                                                  const float* __restrict__ s2) {
    float s = silu_f(v) * b2[col];
    float bs[8];
    bspline8(v, bs);
    const float* sp = s2 + col * 8;
#pragma unroll
    for (int k = 0; k < 8; k++) s += bs[k] * sp[k];
    return s;
}

// shared mainloop: accumulates the 128x128 block product into acc
#define GEMM_MAINLOOP(As, Ws, acc, K)                                          \
    do {                                                                       \
        LOADTILE(0, 0);                                                        \
        CP_COMMIT;                                                             \
        const int nk = (K) >> 4;                                               \
        for (int kc = 0; kc < nk; kc++) {                                      \
            const int buf = kc & 1;                                            \
            if (kc + 1 < nk) LOADTILE(buf ^ 1, (kc + 1) * 16);                 \
            CP_COMMIT;                                                         \
            CP_WAIT1;                                                          \
            __syncthreads();                                                   \
            _Pragma("unroll") for (int ks = 0; ks < 2; ks++) {                 \
                const int kk = ks * 8;                                         \
                const int r0 = wm + (lane >> 2);                               \
                const int c0 = kk + (lane & 3);                                \
                uint32_t ua[2][4];                                             \
                _Pragma("unroll") for (int t = 0; t < 2; t++) {                \
                    ua[t][0] = frag(As[buf][r0 + t * 16][c0]);                 \
                    ua[t][1] = frag(As[buf][r0 + t * 16 + 8][c0]);             \
                    ua[t][2] = frag(As[buf][r0 + t * 16][c0 + 4]);             \
                    ua[t][3] = frag(As[buf][r0 + t * 16 + 8][c0 + 4]);         \
                }                                                              \
                _Pragma("unroll") for (int n = 0; n < 8; n++) {                \
                    const int nr = wn + n * 8 + (lane >> 2);                   \
                    uint32_t ub0 = frag(Ws[buf][nr][kk + (lane & 3)]);         \
                    uint32_t ub1 = frag(Ws[buf][nr][kk + (lane & 3) + 4]);     \
                    _Pragma("unroll") for (int t = 0; t < 2; t++) {            \
                        asm volatile(                                          \
                            "mma.sync.aligned.m16n8k8.row.col.f32.tf32.tf32.f32 " \
                            "{%0,%1,%2,%3},{%4,%5,%6,%7},{%8,%9},{%0,%1,%2,%3};" \
                            : "+f"(acc[t][n][0]), "+f"(acc[t][n][1]),          \
                              "+f"(acc[t][n][2]), "+f"(acc[t][n][3])           \
                            : "r"(ua[t][0]), "r"(ua[t][1]), "r"(ua[t][2]),     \
                              "r"(ua[t][3]), "r"(ub0), "r"(ub1));              \
                    }                                                          \
                }                                                              \
            }                                                                  \
            __syncthreads();                                                   \
        }                                                                      \
    } while (0)

// ---------------- standard tf32 GEMM (identical compile footprint to R10) ----
// C[M, ldc] = A[M,K] @ W[N,K]^T (+bias); N-tile = blockIdx.y; fuse 1 = gelu
__global__ __launch_bounds__(256) void kgemm(
    const float* __restrict__ A, const float* __restrict__ W,
    const float* __restrict__ bias, float* __restrict__ C,
    int M, int K, int ldc, int fuse)
{
    __shared__ float As[2][128][20];
    __shared__ float Ws[2][128][20];
    const int bm = blockIdx.x * 128;
    const int bn = blockIdx.y * 128;
    const int tid = threadIdx.x;
    const int warp = tid >> 5, lane = tid & 31;
    const int wm = (warp >> 1) * 32, wn = (warp & 1) * 64;

    const int lr = tid >> 1;
    const int lo = (tid & 1) * 8;
    int arow = bm + lr;
    if (arow >= M) arow = M - 1;
    const float* Abase = A + (size_t)arow * K;
    const float* Wbase = W + (size_t)(bn + lr) * K;

#define LOADTILE(buf, k0)                                          \
    do {                                                           \
        cp_async16(&As[buf][lr][lo], Abase + (k0) + lo);           \
        cp_async16(&As[buf][lr][lo + 4], Abase + (k0) + lo + 4);   \
        cp_async16(&Ws[buf][lr][lo], Wbase + (k0) + lo);           \
        cp_async16(&Ws[buf][lr][lo + 4], Wbase + (k0) + lo + 4);   \
    } while (0)

    float acc[2][8][4];
#pragma unroll
    for (int t = 0; t < 2; t++)
#pragma unroll
        for (int n = 0; n < 8; n++)
#pragma unroll
            for (int v = 0; v < 4; v++) acc[t][n][v] = 0.0f;

    GEMM_MAINLOOP(As, Ws, acc, K);
#undef LOADTILE

#pragma unroll
    for (int t = 0; t < 2; t++) {
        const int r = bm + wm + t * 16 + (lane >> 2);
        const int r2 = r + 8;
#pragma unroll
        for (int n = 0; n < 8; n++) {
            const int col = bn + wn + n * 8 + (lane & 3) * 2;
            float bz0 = bias ? bias[col] : 0.0f;
            float bz1 = bias ? bias[col + 1] : 0.0f;
            float v0 = acc[t][n][0] + bz0, v1 = acc[t][n][1] + bz1;
            float v2 = acc[t][n][2] + bz0, v3 = acc[t][n][3] + bz1;
            if (fuse == 1) { v0 = gelu_f(v0); v1 = gelu_f(v1); v2 = gelu_f(v2); v3 = gelu_f(v3); }
            if (r < M) {
                C[(size_t)r * ldc + col] = v0;
                C[(size_t)r * ldc + col + 1] = v1;
            }
            if (r2 < M) {
                C[(size_t)r2 * ldc + col] = v2;
                C[(size_t)r2 * ldc + col + 1] = v3;
            }
        }
    }
}

// ---------------- dedicated edge-alpha GEMM (register pressure contained) ----
// alpha[r] = sigmoid( sum_col KAN2( gelu( (actE@Wp2^T)[r,col] + P1[src[r]][col] ) ) )
__global__ __launch_bounds__(256) void kgemm_alpha(
    const float* __restrict__ A, const float* __restrict__ W,
    const float* __restrict__ addMat, const int* __restrict__ addIdx,
    float* __restrict__ alphaOut, const float* __restrict__ b2,
    const float* __restrict__ s2, int M, int K)
{
    __shared__ float As[2][128][20];
    __shared__ float Ws[2][128][20];
    __shared__ float sm_alpha[128];
    const int bm = blockIdx.x * 128;
    const int bn = 0;
    const int tid = threadIdx.x;
    const int warp = tid >> 5, lane = tid & 31;
    const int wm = (warp >> 1) * 32, wn = (warp & 1) * 64;

    const int lr = tid >> 1;
    const int lo = (tid & 1) * 8;
    int arow = bm + lr;
    if (arow >= M) arow = M - 1;
    const float* Abase = A + (size_t)arow * K;
    const float* Wbase = W + (size_t)(bn + lr) * K;

#define LOADTILE(buf, k0)                                          \
    do {                                                           \
        cp_async16(&As[buf][lr][lo], Abase + (k0) + lo);           \
        cp_async16(&As[buf][lr][lo + 4], Abase + (k0) + lo + 4);   \
        cp_async16(&Ws[buf][lr][lo], Wbase + (k0) + lo);           \
        cp_async16(&Ws[buf][lr][lo + 4], Wbase + (k0) + lo + 4);   \
    } while (0)

    float acc[2][8][4];
#pragma unroll
    for (int t = 0; t < 2; t++)
#pragma unroll
        for (int n = 0; n < 8; n++)
#pragma unroll
            for (int v = 0; v < 4; v++) acc[t][n][v] = 0.0f;

    GEMM_MAINLOOP(As, Ws, acc, K);
#undef LOADTILE

    if (tid < 128) sm_alpha[tid] = 0.0f;
    __syncthreads();
    float srow[2][2] = {{0.0f, 0.0f}, {0.0f, 0.0f}};
#pragma unroll
    for (int t = 0; t < 2; t++) {
        const int r = bm + wm + t * 16 + (lane >> 2);
        const int r2 = r + 8;
        const float* add0 = (r < M) ? addMat + (size_t)addIdx[r] * 128 : nullptr;
        const float* add1 = (r2 < M) ? addMat + (size_t)addIdx[r2] * 128 : nullptr;
#pragma unroll
        for (int n = 0; n < 8; n++) {
            const int col = wn + n * 8 + (lane & 3) * 2;
            float v0 = gelu_f(acc[t][n][0] + (add0 ? add0[col] : 0.0f));
            float v1 = gelu_f(acc[t][n][1] + (add0 ? add0[col + 1] : 0.0f));
            float v2 = gelu_f(acc[t][n][2] + (add1 ? add1[col] : 0.0f));
            float v3 = gelu_f(acc[t][n][3] + (add1 ? add1[col + 1] : 0.0f));
            srow[t][0] += kan2_term(v0, col, b2, s2) + kan2_term(v1, col + 1, b2, s2);
            srow[t][1] += kan2_term(v2, col, b2, s2) + kan2_term(v3, col + 1, b2, s2);
        }
    }
#pragma unroll
    for (int o = 1; o < 4; o <<= 1) {
        srow[0][0] += __shfl_xor_sync(0xffffffffu, srow[0][0], o);
        srow[0][1] += __shfl_xor_sync(0xffffffffu, srow[0][1], o);
        srow[1][0] += __shfl_xor_sync(0xffffffffu, srow[1][0], o);
        srow[1][1] += __shfl_xor_sync(0xffffffffu, srow[1][1], o);
    }
    if ((lane & 3) == 0) {
        const int rl = wm + (lane >> 2);
        atomicAdd(&sm_alpha[rl], srow[0][0]);
        atomicAdd(&sm_alpha[rl + 8], srow[0][1]);
        atomicAdd(&sm_alpha[rl + 16], srow[1][0]);
        atomicAdd(&sm_alpha[rl + 24], srow[1][1]);
    }
    __syncthreads();
    if (tid < 128) {
        const int r = bm + tid;
        if (r < M) alphaOut[r] = 1.0f / (1.0f + expf(-sm_alpha[tid]));
    }
}

// ---------------- small kernels ----------------
__global__ void k_pack_slice(float* __restrict__ dst, const float* __restrict__ base,
                             const float* __restrict__ spline, int in_total, int c0) {
    int idx = blockIdx.x * blockDim.x + threadIdx.x;
    if (idx >= 128 * 1152) return;
    int o = idx / 1152;
    int c = idx - o * 1152;
    float v;
    if (c < 128) {
        v = base[(size_t)o * in_total + c0 + c];
    } else {
        int ci = (c - 128) >> 3, k = (c - 128) & 7;
        v = spline[((size_t)o * in_total + c0 + ci) * 8 + k];
    }
    dst[idx] = v;
}

__global__ void k_pack_qkv(float* __restrict__ Wd, float* __restrict__ bd,
                           const float* __restrict__ qW, const float* __restrict__ qb,
                           const float* __restrict__ kW, const float* __restrict__ kb,
                           const float* __restrict__ vW, const float* __restrict__ vb) {
    int idx = blockIdx.x * blockDim.x + threadIdx.x;
    if (idx < 384 * 128) {
        int o = idx >> 7, c = idx & 127;
        float v;
        if (o < 128) v = qW[o * 128 + c];
        else if (o < 256) v = kW[(o - 128) * 128 + c];
        else v = vW[(o - 256) * 128 + c];
        Wd[idx] = v;
    }
    if (idx < 384) {
        bd[idx] = (idx < 128) ? qb[idx] : (idx < 256 ? kb[idx - 128] : vb[idx - 256]);
    }
}

__global__ void k_pool_init(float* __restrict__ pooled, const float* __restrict__ h,
                            const float* __restrict__ eps, int l, int total) {
    int idx = blockIdx.x * blockDim.x + threadIdx.x;
    if (idx >= total) return;
    pooled[idx] = (1.0f + eps[l]) * h[idx];
}

__global__ void k_scatter_pool(float* __restrict__ pooled, const float* __restrict__ h,
                               const int* __restrict__ src, const int* __restrict__ dst,
                               int E) {
    int idx = blockIdx.x * blockDim.x + threadIdx.x;
    if (idx >= E * HID) return;
    int e = idx >> 7;
    int f = idx & 127;
    atomicAdd(&pooled[(size_t)src[e] * HID + f], h[(size_t)dst[e] * HID + f]);
}

// KAN act expansion: X[M,128] -> act[M,1152]
__global__ void k_act(float* __restrict__ act, const float* __restrict__ X, int total) {
    int idx = blockIdx.x * blockDim.x + threadIdx.x;
    if (idx >= total) return;
    int n = idx >> 7;
    int i = idx & 127;
    float x = X[idx];
    float* row = act + (size_t)n * 1152;
    row[i] = silu_f(x);
    float bs[8];
    bspline8(x, bs);
    float4* bp = reinterpret_cast<float4*>(row + 128 + i * 8);
    bp[0] = make_float4(bs[0], bs[1], bs[2], bs[3]);
    bp[1] = make_float4(bs[4], bs[5], bs[6], bs[7]);
}

__global__ void k_bn_partial(const float* __restrict__ X, float* __restrict__ part, int Nn) {
    int f = threadIdx.x;
    float s = 0.0f, s2 = 0.0f;
    for (int r = blockIdx.x; r < Nn; r += gridDim.x) {
        float v = X[(size_t)r * HID + f];
        s += v;
        s2 += v * v;
    }
    part[blockIdx.x * 256 + f] = s;
    part[blockIdx.x * 256 + 128 + f] = s2;
}

__global__ void k_bn_final(const float* __restrict__ part, float* __restrict__ mu,
                           float* __restrict__ rstd, int Nn) {
    int f = threadIdx.x;
    float s = 0.0f, s2 = 0.0f;
    for (int b = 0; b < BNB; b++) {
        s += part[b * 256 + f];
        s2 += part[b * 256 + 128 + f];
    }
    float m = s / (float)Nn;
    float v = s2 / (float)Nn - m * m;
    mu[f] = m;
    rstd[f] = rsqrtf(v + 1e-5f);
}

// bn + relu; writes hkan, copy hatt, AND the KAN expansion of hkan into actN
__global__ void k_bn_apply_act(float* __restrict__ X, float* __restrict__ Xcopy,
                               float* __restrict__ actN,
                               const float* __restrict__ mu, const float* __restrict__ rstd,
                               const float* __restrict__ gamma, const float* __restrict__ beta,
                               int total) {
    int idx = blockIdx.x * blockDim.x + threadIdx.x;
    if (idx >= total) return;
    int n = idx >> 7;
    int i = idx & 127;
    float v = (X[idx] - mu[i]) * rstd[i] * gamma[i] + beta[i];
    v = fmaxf(v, 0.0f);
    X[idx] = v;
    Xcopy[idx] = v;
    float* row = actN + (size_t)n * 1152;
    row[i] = silu_f(v);
    float bs[8];
    bspline8(v, bs);
    float4* bp = reinterpret_cast<float4*>(row + 128 + i * 8);
    bp[0] = make_float4(bs[0], bs[1], bs[2], bs[3]);
    bp[1] = make_float4(bs[4], bs[5], bs[6], bs[7]);
}

// attention from node-level QKV + fused KAN expansion of attended into actE
__global__ void k_attn_act(const float* __restrict__ QKV, const int* __restrict__ src,
                           const int* __restrict__ dst, const float* __restrict__ pos,
                           float* __restrict__ actE, int E) {
    int e = blockIdx.x;
    if (e >= E) return;
    int f = threadIdx.x;
    int h = f >> 5;
    __shared__ float logits[4];
    const float* rs = QKV + (size_t)src[e] * 384;
    const float* rd = QKV + (size_t)dst[e] * 384;
    float q = rs[f] + pos[f];
    float k = rd[128 + f] + pos[f];
    float v = rd[256 + f];
    float p = q * k;
#pragma unroll
    for (int o = 16; o > 0; o >>= 1) p += __shfl_down_sync(0xffffffffu, p, o);
    if ((f & 31) == 0) logits[h] = p * 0.17677669529663687f;
    __syncthreads();
    float l0 = logits[0], l1 = logits[1], l2 = logits[2], l3 = logits[3];
    float mx = fmaxf(fmaxf(l0, l1), fmaxf(l2, l3));
    float den = expf(l0 - mx) + expf(l1 - mx) + expf(l2 - mx) + expf(l3 - mx);
    float w = expf(logits[h] - mx) / den;
    float att = w * v;
    float* row = actE + (size_t)e * 1152;
    row[f] = silu_f(att);
    float bs[8];
    bspline8(att, bs);
    float4* bp = reinterpret_cast<float4*>(row + 128 + f * 8);
    bp[0] = make_float4(bs[0], bs[1], bs[2], bs[3]);
    bp[1] = make_float4(bs[4], bs[5], bs[6], bs[7]);
}

__global__ void k_scatter_att(float* __restrict__ hatt, const float* __restrict__ hk,
                              const float* __restrict__ alpha, const int* __restrict__ src,
                              const int* __restrict__ dst, int E) {
    int idx = blockIdx.x * blockDim.x + threadIdx.x;
    if (idx >= E * HID) return;
    int e = idx >> 7;
    int f = idx & 127;
    atomicAdd(&hatt[(size_t)src[e] * HID + f], alpha[e] * hk[(size_t)dst[e] * HID + f]);
}

__global__ void k_ln(const float* __restrict__ Xatt, const float* __restrict__ Res,
                     const float* __restrict__ gamma, const float* __restrict__ beta,
                     float* __restrict__ Hout, int Nn) {
    int n = blockIdx.x;
    if (n >= Nn) return;
    int f = threadIdx.x;
    __shared__ float red[128];
    float x = Xatt[(size_t)n * HID + f] + Res[(size_t)n * HID + f];
    red[f] = x;
    __syncthreads();
#pragma unroll
    for (int o = 64; o > 0; o >>= 1) {
        if (f < o) red[f] += red[f + o];
        __syncthreads();
    }
    float mu = red[0] / 128.0f;
    __syncthreads();
    float d = x - mu;
    red[f] = d * d;
    __syncthreads();
#pragma unroll
    for (int o = 64; o > 0; o >>= 1) {
        if (f < o) red[f] += red[f + o];
        __syncthreads();
    }
    float var = red[0] / 128.0f;
    Hout[(size_t)n * HID + f] = d * rsqrtf(var + 1e-5f) * gamma[f] + beta[f];
}

__global__ void k_clf(const float* __restrict__ H, const float* __restrict__ W,
                      const float* __restrict__ b, float* __restrict__ out, int Nn) {
    int n = blockIdx.x;
    if (n >= Nn) return;
    int o = threadIdx.x >> 5;
    int lane = threadIdx.x & 31;
    float s = 0.0f;
#pragma unroll
    for (int ii = 0; ii < 4; ii++) {
        int i = lane + 32 * ii;
        s += H[(size_t)n * HID + i] * W[o * HID + i];
    }
#pragma unroll
    for (int of = 16; of > 0; of >>= 1) s += __shfl_down_sync(0xffffffffu, s, of);
    if (lane == 0) out[(size_t)n * 10 + o] = s + b[o];
}

// ---------------- launch ----------------
extern "C" void kernel_launch(void* const* d_in, const int* in_sizes, int n_in,
                              void* d_out, int out_size) {
    const float* x = (const float*)d_in[0];
    const int* src = (const int*)d_in[1];
    const int* dst = (const int*)d_in[2];
    const float* eps = (const float*)d_in[3];
    const float* kan_base = (const float*)d_in[4];
    const float* kan_spline = (const float*)d_in[5];
    const float* bn_gamma = (const float*)d_in[6];
    const float* bn_beta = (const float*)d_in[7];
    const float* ln_gamma = (const float*)d_in[8];
    const float* ln_beta = (const float*)d_in[9];
    const float* qW = (const float*)d_in[10];
    const float* qb = (const float*)d_in[11];
    const float* kW = (const float*)d_in[12];
    const float* kb = (const float*)d_in[13];
    const float* vW = (const float*)d_in[14];
    const float* vb = (const float*)d_in[15];
    const float* pos = (const float*)d_in[16];
    const float* ak1b = (const float*)d_in[17];
    const float* ak1s = (const float*)d_in[18];
    const float* ak2b = (const float*)d_in[19];
    const float* ak2s = (const float*)d_in[20];
    const float* skip_W = (const float*)d_in[21];
    const float* skip_b = (const float*)d_in[22];
    const float* clf_W = (const float*)d_in[23];
    const float* clf_b = (const float*)d_in[24];
    float* out = (float*)d_out;

    const int N = in_sizes[0] / HID;
    const int E = in_sizes[1];

    float *p_pooled, *p_hkan, *p_hatt, *p_res, *p_h, *p_P1, *p_QKV, *p_actN, *p_actE;
    float *p_alpha;
    float *p_Wn, *p_Wp1, *p_Wp2, *p_Wqkv, *p_bqkv, *p_part, *p_mu, *p_rstd;
    cudaGetSymbolAddress((void**)&p_pooled, g_pooled);
    cudaGetSymbolAddress((void**)&p_hkan, g_hkan);
    cudaGetSymbolAddress((void**)&p_hatt, g_hatt);
    cudaGetSymbolAddress((void**)&p_res, g_res);
    cudaGetSymbolAddress((void**)&p_h, g_h);
    cudaGetSymbolAddress((void**)&p_P1, g_P1);
    cudaGetSymbolAddress((void**)&p_QKV, g_QKV);
    cudaGetSymbolAddress((void**)&p_actN, g_actN);
    cudaGetSymbolAddress((void**)&p_actE, g_actE);
    cudaGetSymbolAddress((void**)&p_alpha, g_alpha);
    cudaGetSymbolAddress((void**)&p_Wn, g_Wn);
    cudaGetSymbolAddress((void**)&p_Wp1, g_Wp1);
    cudaGetSymbolAddress((void**)&p_Wp2, g_Wp2);
    cudaGetSymbolAddress((void**)&p_Wqkv, g_Wqkv);
    cudaGetSymbolAddress((void**)&p_bqkv, g_bqkv);
    cudaGetSymbolAddress((void**)&p_part, g_part);
    cudaGetSymbolAddress((void**)&p_mu, g_mu);
    cudaGetSymbolAddress((void**)&p_rstd, g_rstd);

    const int T = 256;
    const int nh = N * HID;
    const int eh = E * HID;
    const int gN = (N + 127) / 128;
    const int gE = (E + 127) / 128;
    const int gPack = (128 * 1152 + T - 1) / T;

    for (int l = 0; l < 2; l++) {
        const float* h_in = (l == 0) ? x : p_h;

        // weight packing
        k_pack_slice<<<gPack, T>>>(p_Wn, kan_base + (size_t)l * 128 * 128,
                                   kan_spline + (size_t)l * 128 * 128 * 8, 128, 0);
        k_pack_slice<<<gPack, T>>>(p_Wp1, ak1b + (size_t)l * 128 * 256,
                                   ak1s + (size_t)l * 128 * 256 * 8, 256, 0);
        k_pack_slice<<<gPack, T>>>(p_Wp2, ak1b + (size_t)l * 128 * 256,
                                   ak1s + (size_t)l * 128 * 256 * 8, 256, 128);
        k_pack_qkv<<<(384 * 128 + T - 1) / T, T>>>(p_Wqkv, p_bqkv,
                                                   qW + (size_t)l * 16384, qb + l * 128,
                                                   kW + (size_t)l * 16384, kb + l * 128,
                                                   vW + (size_t)l * 16384, vb + l * 128);

        // GIN aggregation
        k_pool_init<<<(nh + T - 1) / T, T>>>(p_pooled, h_in, eps, l, nh);
        k_scatter_pool<<<(eh + T - 1) / T, T>>>(p_pooled, h_in, src, dst, E);

        // node KAN
        k_act<<<(nh + T - 1) / T, T>>>(p_actN, p_pooled, nh);
        kgemm<<<dim3(gN, 1), 256>>>(p_actN, p_Wn, nullptr, p_hkan, N, 1152, 128, 0);

        // BatchNorm + relu (fills hatt copy + actN expansion of hkan)
        k_bn_partial<<<BNB, 128>>>(p_hkan, p_part, N);
        k_bn_final<<<1, 128>>>(p_part, p_mu, p_rstd, N);
        k_bn_apply_act<<<(nh + T - 1) / T, T>>>(p_hkan, p_hatt, p_actN, p_mu, p_rstd,
                                                bn_gamma + l * 128, bn_beta + l * 128, nh);

        // node-level first-half of edge KAN1
        kgemm<<<dim3(gN, 1), 256>>>(p_actN, p_Wp1, nullptr, p_P1, N, 1152, 128, 0);

        // node-level QKV
        kgemm<<<dim3(gN, 3), 256>>>(p_hkan, p_Wqkv, p_bqkv, p_QKV, N, 128, 384, 0);

        // attention + fused edge-act expansion
        k_attn_act<<<E, 128>>>(p_QKV, src, dst, pos + l * 128, p_actE, E);

        // edge KAN1 second-half + gelu + KAN2 + sigmoid (dedicated kernel)
        kgemm_alpha<<<gE, 256>>>(p_actE, p_Wp2, p_P1, src, p_alpha,
                                 ak2b + l * 128, ak2s + l * 1024, E, 1152);

        // attention aggregation (hatt pre-filled by bn_apply_act)
        k_scatter_att<<<(eh + T - 1) / T, T>>>(p_hatt, p_hkan, p_alpha, src, dst, E);

        // residual + LayerNorm
        const float* resp;
        if (l == 0) {
            kgemm<<<dim3(gN, 1), 256>>>(x, skip_W, skip_b, p_res, N, 128, 128, 0);
            resp = p_res;
        } else {
            resp = p_h;
        }
        k_ln<<<N, 128>>>(p_hatt, resp, ln_gamma + l * 128, ln_beta + l * 128, p_h, N);
    }

    k_clf<<<N, 320>>>(p_h, clf_W, clf_b, out, N);
}

// round 14
// speedup vs baseline: 1.2675x; 1.2332x over previous
#include <cuda_runtime.h>
#include <math.h>
#include <stdint.h>

#define HID 128
#define NNODE 20000
#define NEDGE 50000
#define BNB 160

// ---------------- scratch (device globals) ----------------
__device__ float g_pooled[NNODE * HID];
__device__ float g_hkan[NNODE * HID];
__device__ float g_hatt[NNODE * HID];
__device__ float g_res[NNODE * HID];
__device__ float g_h[NNODE * HID];
__device__ float g_P1[NNODE * HID];
__device__ float g_QKV[NNODE * 384];
__device__ float g_actN[NNODE * 1152];
__device__ float g_actE[(size_t)NEDGE * 1152];
__device__ float g_z1[NEDGE * HID];
__device__ float g_alpha[NEDGE];
__device__ float g_Wn[128 * 1152];
__device__ float g_Wp1[128 * 1152];
__device__ float g_Wp2[128 * 1152];
__device__ float g_Wqkv[384 * 128];
__device__ float g_bqkv[384];
__device__ float g_part[BNB * 256];
__device__ float g_mu[128];
__device__ float g_rstd[128];

// ---------------- math helpers ----------------
static __device__ __forceinline__ float knot(int i) {
    return (float)(i - 3) * 0.4f - 1.0f;
}

static __device__ __forceinline__ void bspline8(float x, float* out) {
    float b[11];
#pragma unroll
    for (int j = 0; j < 11; j++)
        b[j] = (x >= knot(j) && x < knot(j + 1)) ? 1.0f : 0.0f;
#pragma unroll
    for (int k = 1; k <= 3; k++) {
#pragma unroll
        for (int j = 0; j < 11 - k; j++) {
            float linv = 1.0f / (knot(j + k) - knot(j));
            float rinv = 1.0f / (knot(j + k + 1) - knot(j + 1));
            b[j] = (x - knot(j)) * linv * b[j] + (knot(j + k + 1) - x) * rinv * b[j + 1];
        }
    }
#pragma unroll
    for (int k = 0; k < 8; k++) out[k] = b[k];
}

static __device__ __forceinline__ float silu_f(float x) {
    return x / (1.0f + expf(-x));
}

static __device__ __forceinline__ float gelu_f(float x) {
    return 0.5f * x * (1.0f + erff(x * 0.7071067811865475f));
}

static __device__ __forceinline__ uint32_t frag(float v) {
    uint32_t r;
    asm("cvt.rna.tf32.f32 %0, %1;" : "=r"(r) : "f"(v));
    return r;
}

static __device__ __forceinline__ void cp_async16(void* smem, const void* gmem) {
    uint32_t s = (uint32_t)__cvta_generic_to_shared(smem);
    asm volatile("cp.async.cg.shared.global [%0], [%1], 16;\n" ::"r"(s), "l"(gmem));
}
#define CP_COMMIT asm volatile("cp.async.commit_group;\n" ::)
#define CP_WAIT1 asm volatile("cp.async.wait_group 1;\n" ::)

// ---------------- tf32 tensor-core GEMM (R10-proven) ----------------
// C[M, ldc] = A[M,K] @ W[N,K]^T (+bias); N-tile = blockIdx.y
// optional epilogue: + addMat[addIdx[r]] (row-gathered add), then gelu if fuse==1
__global__ __launch_bounds__(256) void kgemm(
    const float* __restrict__ A, const float* __restrict__ W,
    const float* __restrict__ bias, float* __restrict__ C,
    int M, int K, int ldc, int fuse,
    const float* __restrict__ addMat, const int* __restrict__ addIdx)
{
    __shared__ float As[2][128][20];
    __shared__ float Ws[2][128][20];
    const int bm = blockIdx.x * 128;
    const int bn = blockIdx.y * 128;
    const int tid = threadIdx.x;
    const int warp = tid >> 5, lane = tid & 31;
    const int wm = (warp >> 1) * 32, wn = (warp & 1) * 64;

    const int lr = tid >> 1;
    const int lo = (tid & 1) * 8;
    int arow = bm + lr;
    if (arow >= M) arow = M - 1;
    const float* Abase = A + (size_t)arow * K;
    const float* Wbase = W + (size_t)(bn + lr) * K;

#define LOADTILE(buf, k0)                                          \
    do {                                                           \
        cp_async16(&As[buf][lr][lo], Abase + (k0) + lo);           \
        cp_async16(&As[buf][lr][lo + 4], Abase + (k0) + lo + 4);   \
        cp_async16(&Ws[buf][lr][lo], Wbase + (k0) + lo);           \
        cp_async16(&Ws[buf][lr][lo + 4], Wbase + (k0) + lo + 4);   \
    } while (0)

    float acc[2][8][4];
#pragma unroll
    for (int t = 0; t < 2; t++)
#pragma unroll
        for (int n = 0; n < 8; n++)
#pragma unroll
            for (int v = 0; v < 4; v++) acc[t][n][v] = 0.0f;

    LOADTILE(0, 0);
    CP_COMMIT;

    const int nk = K >> 4;
    for (int kc = 0; kc < nk; kc++) {
        const int buf = kc & 1;
        if (kc + 1 < nk) LOADTILE(buf ^ 1, (kc + 1) * 16);
        CP_COMMIT;
        CP_WAIT1;
        __syncthreads();

#pragma unroll
        for (int ks = 0; ks < 2; ks++) {
            const int kk = ks * 8;
            const int r0 = wm + (lane >> 2);
            const int c0 = kk + (lane & 3);
            uint32_t ua[2][4];
#pragma unroll
            for (int t = 0; t < 2; t++) {
                ua[t][0] = frag(As[buf][r0 + t * 16][c0]);
                ua[t][1] = frag(As[buf][r0 + t * 16 + 8][c0]);
                ua[t][2] = frag(As[buf][r0 + t * 16][c0 + 4]);
                ua[t][3] = frag(As[buf][r0 + t * 16 + 8][c0 + 4]);
            }
#pragma unroll
            for (int n = 0; n < 8; n++) {
                const int nr = wn + n * 8 + (lane >> 2);
                uint32_t ub0 = frag(Ws[buf][nr][kk + (lane & 3)]);
                uint32_t ub1 = frag(Ws[buf][nr][kk + (lane & 3) + 4]);
#pragma unroll
                for (int t = 0; t < 2; t++) {
                    asm volatile(
                        "mma.sync.aligned.m16n8k8.row.col.f32.tf32.tf32.f32 "
                        "{%0,%1,%2,%3},{%4,%5,%6,%7},{%8,%9},{%0,%1,%2,%3};"
                        : "+f"(acc[t][n][0]), "+f"(acc[t][n][1]),
                          "+f"(acc[t][n][2]), "+f"(acc[t][n][3])
                        : "r"(ua[t][0]), "r"(ua[t][1]), "r"(ua[t][2]), "r"(ua[t][3]),
                          "r"(ub0), "r"(ub1));
                }
            }
        }
        __syncthreads();
    }
#undef LOADTILE

    // epilogue
#pragma unroll
    for (int t = 0; t < 2; t++) {
        const int r = bm + wm + t * 16 + (lane >> 2);
        const int r2 = r + 8;
        const float* add0 = nullptr;
        const float* add1 = nullptr;
        if (addMat) {
            if (r < M) add0 = addMat + (size_t)(addIdx ? addIdx[r] : r) * ldc;
            if (r2 < M) add1 = addMat + (size_t)(addIdx ? addIdx[r2] : r2) * ldc;
        }
#pragma unroll
        for (int n = 0; n < 8; n++) {
            const int col = bn + wn + n * 8 + (lane & 3) * 2;
            float bz0 = bias ? bias[col] : 0.0f;
            float bz1 = bias ? bias[col + 1] : 0.0f;
            float v0 = acc[t][n][0] + bz0 + (add0 ? add0[col] : 0.0f);
            float v1 = acc[t][n][1] + bz1 + (add0 ? add0[col + 1] : 0.0f);
            float v2 = acc[t][n][2] + bz0 + (add1 ? add1[col] : 0.0f);
            float v3 = acc[t][n][3] + bz1 + (add1 ? add1[col + 1] : 0.0f);
            if (fuse == 1) { v0 = gelu_f(v0); v1 = gelu_f(v1); v2 = gelu_f(v2); v3 = gelu_f(v3); }
            if (r < M) {
                C[(size_t)r * ldc + col] = v0;
                C[(size_t)r * ldc + col + 1] = v1;
            }
            if (r2 < M) {
                C[(size_t)r2 * ldc + col] = v2;
                C[(size_t)r2 * ldc + col + 1] = v3;
            }
        }
    }
}

// ---------------- small kernels ----------------
__global__ void k_pack_slice(float* __restrict__ dst, const float* __restrict__ base,
                             const float* __restrict__ spline, int in_total, int c0) {
    int idx = blockIdx.x * blockDim.x + threadIdx.x;
    if (idx >= 128 * 1152) return;
    int o = idx / 1152;
    int c = idx - o * 1152;
    float v;
    if (c < 128) {
        v = base[(size_t)o * in_total + c0 + c];
    } else {
        int ci = (c - 128) >> 3, k = (c - 128) & 7;
        v = spline[((size_t)o * in_total + c0 + ci) * 8 + k];
    }
    dst[idx] = v;
}

__global__ void k_pack_qkv(float* __restrict__ Wd, float* __restrict__ bd,
                           const float* __restrict__ qW, const float* __restrict__ qb,
                           const float* __restrict__ kW, const float* __restrict__ kb,
                           const float* __restrict__ vW, const float* __restrict__ vb) {
    int idx = blockIdx.x * blockDim.x + threadIdx.x;
    if (idx < 384 * 128) {
        int o = idx >> 7, c = idx & 127;
        float v;
        if (o < 128) v = qW[o * 128 + c];
        else if (o < 256) v = kW[(o - 128) * 128 + c];
        else v = vW[(o - 256) * 128 + c];
        Wd[idx] = v;
    }
    if (idx < 384) {
        bd[idx] = (idx < 128) ? qb[idx] : (idx < 256 ? kb[idx - 128] : vb[idx - 256]);
    }
}

__global__ void k_pool_init(float* __restrict__ pooled, const float* __restrict__ h,
                            const float* __restrict__ eps, int l, int total) {
    int idx = blockIdx.x * blockDim.x + threadIdx.x;
    if (idx >= total) return;
    pooled[idx] = (1.0f + eps[l]) * h[idx];
}

__global__ void k_scatter_pool(float* __restrict__ pooled, const float* __restrict__ h,
                               const int* __restrict__ src, const int* __restrict__ dst,
                               int E) {
    int idx = blockIdx.x * blockDim.x + threadIdx.x;
    if (idx >= E * HID) return;
    int e = idx >> 7;
    int f = idx & 127;
    atomicAdd(&pooled[(size_t)src[e] * HID + f], h[(size_t)dst[e] * HID + f]);
}

// KAN act expansion: X[M,128] -> act[M,1152] = [silu(x) | bspline8(x_i) each]
__global__ void k_act(float* __restrict__ act, const float* __restrict__ X, int total) {
    int idx = blockIdx.x * blockDim.x + threadIdx.x;
    if (idx >= total) return;
    int n = idx >> 7;
    int i = idx & 127;
    float x = X[idx];
    float* row = act + (size_t)n * 1152;
    row[i] = silu_f(x);
    float bs[8];
    bspline8(x, bs);
    float4* bp = reinterpret_cast<float4*>(row + 128 + i * 8);
    bp[0] = make_float4(bs[0], bs[1], bs[2], bs[3]);
    bp[1] = make_float4(bs[4], bs[5], bs[6], bs[7]);
}

__global__ void k_bn_partial(const float* __restrict__ X, float* __restrict__ part, int Nn) {
    int f = threadIdx.x;
    float s = 0.0f, s2 = 0.0f;
    for (int r = blockIdx.x; r < Nn; r += gridDim.x) {
        float v = X[(size_t)r * HID + f];
        s += v;
        s2 += v * v;
    }
    part[blockIdx.x * 256 + f] = s;
    part[blockIdx.x * 256 + 128 + f] = s2;
}

__global__ void k_bn_final(const float* __restrict__ part, float* __restrict__ mu,
                           float* __restrict__ rstd, int Nn) {
    int f = threadIdx.x;
    float s = 0.0f, s2 = 0.0f;
    for (int b = 0; b < BNB; b++) {
        s += part[b * 256 + f];
        s2 += part[b * 256 + 128 + f];
    }
    float m = s / (float)Nn;
    float v = s2 / (float)Nn - m * m;
    mu[f] = m;
    rstd[f] = rsqrtf(v + 1e-5f);
}

// bn + relu; writes hkan, copy hatt, AND the KAN expansion of hkan into actN
__global__ void k_bn_apply_act(float* __restrict__ X, float* __restrict__ Xcopy,
                               float* __restrict__ actN,
                               const float* __restrict__ mu, const float* __restrict__ rstd,
                               const float* __restrict__ gamma, const float* __restrict__ beta,
                               int total) {
    int idx = blockIdx.x * blockDim.x + threadIdx.x;
    if (idx >= total) return;
    int n = idx >> 7;
    int i = idx & 127;
    float v = (X[idx] - mu[i]) * rstd[i] * gamma[i] + beta[i];
    v = fmaxf(v, 0.0f);
    X[idx] = v;
    Xcopy[idx] = v;
    float* row = actN + (size_t)n * 1152;
    row[i] = silu_f(v);
    float bs[8];
    bspline8(v, bs);
    float4* bp = reinterpret_cast<float4*>(row + 128 + i * 8);
    bp[0] = make_float4(bs[0], bs[1], bs[2], bs[3]);
    bp[1] = make_float4(bs[4], bs[5], bs[6], bs[7]);
}

// attention from node-level QKV + fused KAN expansion of attended into actE
__global__ void k_attn_act(const float* __restrict__ QKV, const int* __restrict__ src,
                           const int* __restrict__ dst, const float* __restrict__ pos,
                           float* __restrict__ actE, int E) {
    int e = blockIdx.x;
    if (e >= E) return;
    int f = threadIdx.x;
    int h = f >> 5;
    __shared__ float logits[4];
    const float* rs = QKV + (size_t)src[e] * 384;
    const float* rd = QKV + (size_t)dst[e] * 384;
    float q = rs[f] + pos[f];
    float k = rd[128 + f] + pos[f];
    float v = rd[256 + f];
    float p = q * k;
#pragma unroll
    for (int o = 16; o > 0; o >>= 1) p += __shfl_down_sync(0xffffffffu, p, o);
    if ((f & 31) == 0) logits[h] = p * 0.17677669529663687f;
    __syncthreads();
    float l0 = logits[0], l1 = logits[1], l2 = logits[2], l3 = logits[3];
    float mx = fmaxf(fmaxf(l0, l1), fmaxf(l2, l3));
    float den = expf(l0 - mx) + expf(l1 - mx) + expf(l2 - mx) + expf(l3 - mx);
    float w = expf(logits[h] - mx) / den;
    float att = w * v;
    float* row = actE + (size_t)e * 1152;
    row[f] = silu_f(att);
    float bs[8];
    bspline8(att, bs);
    float4* bp = reinterpret_cast<float4*>(row + 128 + f * 8);
    bp[0] = make_float4(bs[0], bs[1], bs[2], bs[3]);
    bp[1] = make_float4(bs[4], bs[5], bs[6], bs[7]);
}

// edge KAN2 (out dim 1) + sigmoid -> alpha
__global__ void k_alpha(const float* __restrict__ Z1, const float* __restrict__ b2,
                        const float* __restrict__ s2, float* __restrict__ alpha, int E) {
    int e = blockIdx.x * (blockDim.x >> 5) + (threadIdx.x >> 5);
    int lane = threadIdx.x & 31;
    if (e >= E) return;
    float s = 0.0f;
#pragma unroll
    for (int ii = 0; ii < 4; ii++) {
        int i = lane + ii * 32;
        float v = Z1[(size_t)e * HID + i];
        s += silu_f(v) * b2[i];
        float bs[8];
        bspline8(v, bs);
        const float* sp = s2 + i * 8;
#pragma unroll
        for (int k = 0; k < 8; k++) s += bs[k] * sp[k];
    }
#pragma unroll
    for (int o = 16; o > 0; o >>= 1) s += __shfl_down_sync(0xffffffffu, s, o);
    if (lane == 0) alpha[e] = 1.0f / (1.0f + expf(-s));
}

__global__ void k_scatter_att(float* __restrict__ hatt, const float* __restrict__ hk,
                              const float* __restrict__ alpha, const int* __restrict__ src,
                              const int* __restrict__ dst, int E) {
    int idx = blockIdx.x * blockDim.x + threadIdx.x;
    if (idx >= E * HID) return;
    int e = idx >> 7;
    int f = idx & 127;
    atomicAdd(&hatt[(size_t)src[e] * HID + f], alpha[e] * hk[(size_t)dst[e] * HID + f]);
}

__global__ void k_ln(const float* __restrict__ Xatt, const float* __restrict__ Res,
                     const float* __restrict__ gamma, const float* __restrict__ beta,
                     float* __restrict__ Hout, int Nn) {
    int n = blockIdx.x;
    if (n >= Nn) return;
    int f = threadIdx.x;
    __shared__ float red[128];
    float x = Xatt[(size_t)n * HID + f] + Res[(size_t)n * HID + f];
    red[f] = x;
    __syncthreads();
#pragma unroll
    for (int o = 64; o > 0; o >>= 1) {
        if (f < o) red[f] += red[f + o];
        __syncthreads();
    }
    float mu = red[0] / 128.0f;
    __syncthreads();
    float d = x - mu;
    red[f] = d * d;
    __syncthreads();
#pragma unroll
    for (int o = 64; o > 0; o >>= 1) {
        if (f < o) red[f] += red[f + o];
        __syncthreads();
    }
    float var = red[0] / 128.0f;
    Hout[(size_t)n * HID + f] = d * rsqrtf(var + 1e-5f) * gamma[f] + beta[f];
}

__global__ void k_clf(const float* __restrict__ H, const float* __restrict__ W,
                      const float* __restrict__ b, float* __restrict__ out, int Nn) {
    int n = blockIdx.x;
    if (n >= Nn) return;
    int o = threadIdx.x >> 5;
    int lane = threadIdx.x & 31;
    float s = 0.0f;
#pragma unroll
    for (int ii = 0; ii < 4; ii++) {
        int i = lane + 32 * ii;
        s += H[(size_t)n * HID + i] * W[o * HID + i];
    }
#pragma unroll
    for (int of = 16; of > 0; of >>= 1) s += __shfl_down_sync(0xffffffffu, s, of);
    if (lane == 0) out[(size_t)n * 10 + o] = s + b[o];
}

// ---------------- launch ----------------
extern "C" void kernel_launch(void* const* d_in, const int* in_sizes, int n_in,
                              void* d_out, int out_size) {
    const float* x = (const float*)d_in[0];
    const int* src = (const int*)d_in[1];
    const int* dst = (const int*)d_in[2];
    const float* eps = (const float*)d_in[3];
    const float* kan_base = (const float*)d_in[4];
    const float* kan_spline = (const float*)d_in[5];
    const float* bn_gamma = (const float*)d_in[6];
    const float* bn_beta = (const float*)d_in[7];
    const float* ln_gamma = (const float*)d_in[8];
    const float* ln_beta = (const float*)d_in[9];
    const float* qW = (const float*)d_in[10];
    const float* qb = (const float*)d_in[11];
    const float* kW = (const float*)d_in[12];
    const float* kb = (const float*)d_in[13];
    const float* vW = (const float*)d_in[14];
    const float* vb = (const float*)d_in[15];
    const float* pos = (const float*)d_in[16];
    const float* ak1b = (const float*)d_in[17];
    const float* ak1s = (const float*)d_in[18];
    const float* ak2b = (const float*)d_in[19];
    const float* ak2s = (const float*)d_in[20];
    const float* skip_W = (const float*)d_in[21];
    const float* skip_b = (const float*)d_in[22];
    const float* clf_W = (const float*)d_in[23];
    const float* clf_b = (const float*)d_in[24];
    float* out = (float*)d_out;

    const int N = in_sizes[0] / HID;
    const int E = in_sizes[1];

    float *p_pooled, *p_hkan, *p_hatt, *p_res, *p_h, *p_P1, *p_QKV, *p_actN, *p_actE;
    float *p_z1, *p_alpha;
    float *p_Wn, *p_Wp1, *p_Wp2, *p_Wqkv, *p_bqkv, *p_part, *p_mu, *p_rstd;
    cudaGetSymbolAddress((void**)&p_pooled, g_pooled);
    cudaGetSymbolAddress((void**)&p_hkan, g_hkan);
    cudaGetSymbolAddress((void**)&p_hatt, g_hatt);
    cudaGetSymbolAddress((void**)&p_res, g_res);
    cudaGetSymbolAddress((void**)&p_h, g_h);
    cudaGetSymbolAddress((void**)&p_P1, g_P1);
    cudaGetSymbolAddress((void**)&p_QKV, g_QKV);
    cudaGetSymbolAddress((void**)&p_actN, g_actN);
    cudaGetSymbolAddress((void**)&p_actE, g_actE);
    cudaGetSymbolAddress((void**)&p_z1, g_z1);
    cudaGetSymbolAddress((void**)&p_alpha, g_alpha);
    cudaGetSymbolAddress((void**)&p_Wn, g_Wn);
    cudaGetSymbolAddress((void**)&p_Wp1, g_Wp1);
    cudaGetSymbolAddress((void**)&p_Wp2, g_Wp2);
    cudaGetSymbolAddress((void**)&p_Wqkv, g_Wqkv);
    cudaGetSymbolAddress((void**)&p_bqkv, g_bqkv);
    cudaGetSymbolAddress((void**)&p_part, g_part);
    cudaGetSymbolAddress((void**)&p_mu, g_mu);
    cudaGetSymbolAddress((void**)&p_rstd, g_rstd);

    const int T = 256;
    const int nh = N * HID;
    const int eh = E * HID;
    const int gN = (N + 127) / 128;
    const int gE = (E + 127) / 128;
    const int gPack = (128 * 1152 + T - 1) / T;

    for (int l = 0; l < 2; l++) {
        const float* h_in = (l == 0) ? x : p_h;

        // weight packing
        k_pack_slice<<<gPack, T>>>(p_Wn, kan_base + (size_t)l * 128 * 128,
                                   kan_spline + (size_t)l * 128 * 128 * 8, 128, 0);
        k_pack_slice<<<gPack, T>>>(p_Wp1, ak1b + (size_t)l * 128 * 256,
                                   ak1s + (size_t)l * 128 * 256 * 8, 256, 0);
        k_pack_slice<<<gPack, T>>>(p_Wp2, ak1b + (size_t)l * 128 * 256,
                                   ak1s + (size_t)l * 128 * 256 * 8, 256, 128);
        k_pack_qkv<<<(384 * 128 + T - 1) / T, T>>>(p_Wqkv, p_bqkv,
                                                   qW + (size_t)l * 16384, qb + l * 128,
                                                   kW + (size_t)l * 16384, kb + l * 128,
                                                   vW + (size_t)l * 16384, vb + l * 128);

        // GIN aggregation
        k_pool_init<<<(nh + T - 1) / T, T>>>(p_pooled, h_in, eps, l, nh);
        k_scatter_pool<<<(eh + T - 1) / T, T>>>(p_pooled, h_in, src, dst, E);

        // node KAN
        k_act<<<(nh + T - 1) / T, T>>>(p_actN, p_pooled, nh);
        kgemm<<<dim3(gN, 1), 256>>>(p_actN, p_Wn, nullptr, p_hkan,
                                    N, 1152, 128, 0, nullptr, nullptr);

        // BatchNorm + relu (fills hatt copy + actN expansion of hkan)
        k_bn_partial<<<BNB, 128>>>(p_hkan, p_part, N);
        k_bn_final<<<1, 128>>>(p_part, p_mu, p_rstd, N);
        k_bn_apply_act<<<(nh + T - 1) / T, T>>>(p_hkan, p_hatt, p_actN, p_mu, p_rstd,
                                                bn_gamma + l * 128, bn_beta + l * 128, nh);

        // node-level first-half of edge KAN1: P1[n] = kan1_firsthalf(hkan[n])
        kgemm<<<dim3(gN, 1), 256>>>(p_actN, p_Wp1, nullptr, p_P1,
                                    N, 1152, 128, 0, nullptr, nullptr);

        // node-level QKV: QKV_n[N,384] = hkan @ [qW;kW;vW]^T + b
        kgemm<<<dim3(gN, 3), 256>>>(p_hkan, p_Wqkv, p_bqkv, p_QKV,
                                    N, 128, 384, 0, nullptr, nullptr);

        // attention + fused edge-act expansion (gathers QKV_n rows)
        k_attn_act<<<E, 128>>>(p_QKV, src, dst, pos + l * 128, p_actE, E);

        // edge-level second-half: z1 = gelu(P1[src] + kan1_secondhalf(att))
        kgemm<<<dim3(gE, 1), 256>>>(p_actE, p_Wp2, nullptr, p_z1,
                                    E, 1152, 128, 1, p_P1, src);
        k_alpha<<<(E + 3) / 4, 128>>>(p_z1, ak2b + l * 128, ak2s + l * 1024, p_alpha, E);

        // attention aggregation (hatt pre-filled by bn_apply_act)
        k_scatter_att<<<(eh + T - 1) / T, T>>>(p_hatt, p_hkan, p_alpha, src, dst, E);

        // residual + LayerNorm
        const float* resp;
        if (l == 0) {
            kgemm<<<dim3(gN, 1), 256>>>(x, skip_W, skip_b, p_res,
                                        N, 128, 128, 0, nullptr, nullptr);
            resp = p_res;
        } else {
            resp = p_h;
        }
        k_ln<<<N, 128>>>(p_hatt, resp, ln_gamma + l * 128, ln_beta + l * 128, p_h, N);
    }

    k_clf<<<N, 320>>>(p_h, clf_W, clf_b, out, N);
}